// round 9
// baseline (speedup 1.0000x reference)
#include <cuda_runtime.h>
#include <cuda_fp16.h>
#include <cstdint>

#define BB 4
#define LL 1024
#define DD 128
#define HH 8
#define GG 64
#define NEGV -1000000000.0f
#define NITER 4
#define NZ (BB*HH)

// ---------------- scratch (static device arrays; no allocations) ----------------
__device__ float g_FZ[BB*LL*DD];
__device__ __half g_Sh[(size_t)NZ*LL*LL];         // fp16 pair logits (67MB)
__device__ float2 g_stats[NZ*LL];                 // per (z,i): (rowmax m, 1/Z)
__device__ float g_Hg[NZ*LL*GG];                  // fp32 global logits
__device__ __half hHg[NZ*LL*GG];                  // Qhg probabilities
__device__ __half hQz[BB*LL*DD];                  // softmax(F_Z)
__device__ __half hP [NZ*LL*DD];                  // P[i,b]
__device__ __half hPt[NZ*DD*LL];                  // P^T[b,i]
__device__ __half hUt[NZ*DD*LL];                  // U^T[a,j]
__device__ __half hT [HH*DD*DD];                  // T[h][a][b]
__device__ __half hTt[HH*DD*DD];                  // T[h][b][a]
__device__ __half hG [HH*128*DD];                 // G[h][g][a], g padded to 128
__device__ __half hGt[HH*DD*GG];                  // G^T[h][a][g]

// ---------------- mma.sync GEMM building blocks ----------------
#define SKA 72                   // A-normal / B smem row stride (halves)
#define SKT 136                  // A-trans smem row stride (halves)
#define TILEB 18432              // one 128x64 (or 64x128) tile in bytes
#define STAGEB (2*TILEB)
#define NSTG 3
#define SMEMB (NSTG*STAGEB)      // 110592 (k_proj)

template<bool TA>
__device__ __forceinline__ void load_A(uint32_t dst, const __half* A, int lda, int kt, int tid) {
  if (!TA) {
    #pragma unroll
    for (int i = 0; i < 8; i++) {
      int idx = tid + i*128;
      int row = idx >> 3, co = (idx & 7) * 8;
      uint32_t d = dst + (row*SKA + co)*2;
      const __half* s = A + (size_t)row*lda + kt*64 + co;
      asm volatile("cp.async.cg.shared.global [%0], [%1], 16;" :: "r"(d), "l"(s));
    }
  } else {
    #pragma unroll
    for (int i = 0; i < 8; i++) {
      int idx = tid + i*128;
      int row = idx >> 4, co = (idx & 15) * 8;
      uint32_t d = dst + (row*SKT + co)*2;
      const __half* s = A + (size_t)(kt*64 + row)*lda + co;
      asm volatile("cp.async.cg.shared.global [%0], [%1], 16;" :: "r"(d), "l"(s));
    }
  }
}
__device__ __forceinline__ void load_B(uint32_t dst, const __half* B, int ldb, int kt, int tid) {
  #pragma unroll
  for (int i = 0; i < 8; i++) {
    int idx = tid + i*128;
    int row = idx >> 3, co = (idx & 7) * 8;
    uint32_t d = dst + (row*SKA + co)*2;
    const __half* s = B + (size_t)row*ldb + kt*64 + co;
    asm volatile("cp.async.cg.shared.global [%0], [%1], 16;" :: "r"(d), "l"(s));
  }
}

// one K=64 chunk of MMA work from smem buffers
template<bool TA>
__device__ __forceinline__ void mma_step(uint32_t bufA, uint32_t bufB,
    float (&c)[4][8][4], int wm, int wn, int lane) {
  int lr = lane & 7, sel = lane >> 3;
  #pragma unroll
  for (int kb = 0; kb < 4; kb++) {
    uint32_t afr[4][4], bfr[4][4];
    #pragma unroll
    for (int mf = 0; mf < 4; mf++) {
      if (!TA) {
        int row = wm*64 + mf*16 + lr + ((sel & 1) ? 8 : 0);
        int col = kb*16 + ((sel & 2) ? 8 : 0);
        uint32_t ad = bufA + (row*SKA + col)*2;
        asm volatile("ldmatrix.sync.aligned.m8n8.x4.shared.b16 {%0,%1,%2,%3},[%4];"
          : "=r"(afr[mf][0]), "=r"(afr[mf][1]), "=r"(afr[mf][2]), "=r"(afr[mf][3]) : "r"(ad));
      } else {
        int row = kb*16 + lr + ((sel & 2) ? 8 : 0);
        int col = wm*64 + mf*16 + ((sel & 1) ? 8 : 0);
        uint32_t ad = bufA + (row*SKT + col)*2;
        asm volatile("ldmatrix.sync.aligned.m8n8.x4.trans.shared.b16 {%0,%1,%2,%3},[%4];"
          : "=r"(afr[mf][0]), "=r"(afr[mf][1]), "=r"(afr[mf][2]), "=r"(afr[mf][3]) : "r"(ad));
      }
    }
    #pragma unroll
    for (int p = 0; p < 4; p++) {
      int row = wn*64 + p*16 + lr + ((sel & 2) ? 8 : 0);
      int col = kb*16 + ((sel & 1) ? 8 : 0);
      uint32_t bd = bufB + (row*SKA + col)*2;
      asm volatile("ldmatrix.sync.aligned.m8n8.x4.shared.b16 {%0,%1,%2,%3},[%4];"
        : "=r"(bfr[p][0]), "=r"(bfr[p][1]), "=r"(bfr[p][2]), "=r"(bfr[p][3]) : "r"(bd));
    }
    #pragma unroll
    for (int mf = 0; mf < 4; mf++)
      #pragma unroll
      for (int nb = 0; nb < 8; nb++) {
        asm volatile("mma.sync.aligned.m16n8k16.row.col.f32.f16.f16.f32 "
          "{%0,%1,%2,%3},{%4,%5,%6,%7},{%8,%9},{%0,%1,%2,%3};"
          : "+f"(c[mf][nb][0]), "+f"(c[mf][nb][1]), "+f"(c[mf][nb][2]), "+f"(c[mf][nb][3])
          : "r"(afr[mf][0]), "r"(afr[mf][1]), "r"(afr[mf][2]), "r"(afr[mf][3]),
            "r"(bfr[nb>>1][(nb&1)*2]), "r"(bfr[nb>>1][(nb&1)*2+1]));
      }
  }
}

// 3-stage pipelined GEMM (used by k_proj)
template<bool TA>
__device__ __forceinline__ void gemm_acc(
    const __half* A, int lda, const __half* B, int ldb, int K,
    float (&c)[4][8][4], uint32_t sbase, int tid, int wm, int wn, int lane)
{
  int NK = K >> 6;
  #pragma unroll
  for (int s = 0; s < NSTG-1; s++) {
    if (s < NK) {
      load_A<TA>(sbase + s*STAGEB, A, lda, s, tid);
      load_B(sbase + s*STAGEB + TILEB, B, ldb, s, tid);
    }
    asm volatile("cp.async.commit_group;");
  }
  for (int kt = 0; kt < NK; kt++) {
    int ps = kt + NSTG - 1;
    if (ps < NK) {
      uint32_t sb = sbase + (ps % NSTG)*STAGEB;
      load_A<TA>(sb, A, lda, ps, tid);
      load_B(sb + TILEB, B, ldb, ps, tid);
    }
    asm volatile("cp.async.commit_group;");
    asm volatile("cp.async.wait_group %0;" :: "n"(NSTG-1));
    __syncthreads();
    uint32_t bufA = sbase + (kt % NSTG)*STAGEB;
    mma_step<TA>(bufA, bufA + TILEB, c, wm, wn, lane);
    __syncthreads();
  }
}

// 2-stage pipelined GEMM with optional in-smem exp transform of A (k_msg2)
// XF=0: none; XF=1: stats row = statbase+row; XF=2: stats row = kt*64+row
#define STG2B (2*TILEB)          // 36864
#define MSG_ST (2*STG2B)         // 73728: stats table offset
#define SM_MSG (MSG_ST + 8192)   // 81920

template<bool TA, int XF>
__device__ __forceinline__ void gemm2(
    const __half* A, int lda, const __half* B, int ldb, int K,
    float (&c)[4][8][4], char* smemc, uint32_t sb, int statbase,
    int tid, int wm, int wn, int lane)
{
  int NK = K >> 6;
  load_A<TA>(sb, A, lda, 0, tid);
  load_B(sb + TILEB, B, ldb, 0, tid);
  asm volatile("cp.async.commit_group;");
  float2* fst = (float2*)(smemc + MSG_ST);
  for (int kt = 0; kt < NK; kt++) {
    if (kt+1 < NK) {
      uint32_t s2 = sb + ((kt+1)&1)*STG2B;
      load_A<TA>(s2, A, lda, kt+1, tid);
      load_B(s2 + TILEB, B, ldb, kt+1, tid);
    }
    asm volatile("cp.async.commit_group;");
    asm volatile("cp.async.wait_group 1;");
    __syncthreads();
    uint32_t bufA = sb + (kt&1)*STG2B;
    if (XF) {
      char* bA = smemc + (kt&1)*STG2B;
      #pragma unroll
      for (int i = 0; i < 8; i++) {
        int idx = tid + i*128;
        int row = TA ? (idx >> 4) : (idx >> 3);
        int co  = TA ? ((idx & 15) * 8) : ((idx & 7) * 8);
        int srow = (XF == 1) ? (statbase + row) : (kt*64 + row);
        float2 st = fst[srow];
        uint4* p4 = (uint4*)(bA + ((TA ? row*SKT : row*SKA) + co)*2);
        uint4 v = *p4;
        __half2* hp = (__half2*)&v;
        #pragma unroll
        for (int k2 = 0; k2 < 4; k2++) {
          float2 f = __half22float2(hp[k2]);
          f.x = __expf(f.x - st.x) * st.y;
          f.y = __expf(f.y - st.x) * st.y;
          hp[k2] = __floats2half2_rn(f.x, f.y);
        }
        *p4 = v;
      }
      __syncthreads();
    }
    mma_step<TA>(bufA, bufA + TILEB, c, wm, wn, lane);
    __syncthreads();
  }
}

// ---------------- merged projection kernel: mode = blockIdx.y ----------------
__global__ __launch_bounds__(128, 2) void k_proj() {
  extern __shared__ char smem[];
  uint32_t sbase = (uint32_t)__cvta_generic_to_shared(smem);
  int tid = threadIdx.x, lane = tid & 31, warp = tid >> 5;
  int wm = warp >> 1, wn = warp & 1;
  int mode = blockIdx.y;
  int z = blockIdx.z, n = z >> 3, h = z & 7;
  int m0 = 0, n0 = 0;
  const __half *A, *B;
  if (mode == 0) {
    m0 = blockIdx.x * 128;
    A = hQz + (size_t)(n*LL + m0)*DD;  B = hTt + h*DD*DD;
  } else if (mode == 1) {
    n0 = blockIdx.x * 128;
    A = hT + h*DD*DD;  B = hQz + (size_t)(n*LL + n0)*DD;
  } else if (mode == 2) {
    n0 = blockIdx.x * 128;
    A = hTt + h*DD*DD;  B = hQz + (size_t)(n*LL + n0)*DD;
  } else {
    m0 = blockIdx.x * 128;
    A = hQz + (size_t)(n*LL + m0)*DD;  B = hG + h*128*DD;
  }
  float c[4][8][4];
  #pragma unroll
  for (int i=0;i<4;i++)
    #pragma unroll
    for (int j=0;j<8;j++)
      #pragma unroll
      for (int k=0;k<4;k++) c[i][j][k] = 0.f;

  gemm_acc<false>(A, DD, B, DD, DD, c, sbase, tid, wm, wn, lane);

  #pragma unroll
  for (int mf = 0; mf < 4; mf++)
    #pragma unroll
    for (int rr = 0; rr < 2; rr++) {
      int row = wm*64 + mf*16 + (lane >> 2) + rr*8;
      #pragma unroll
      for (int nb = 0; nb < 8; nb++) {
        int col = wn*64 + nb*8 + (lane & 3)*2;
        float v0 = c[mf][nb][rr*2], v1 = c[mf][nb][rr*2+1];
        if (mode == 0) {
          *(half2*)(hP + (size_t)(z*LL + m0 + row)*DD + col) = __floats2half2_rn(v0, v1);
        } else if (mode == 1) {
          *(half2*)(hUt + (size_t)z*DD*LL + (size_t)row*LL + n0 + col) = __floats2half2_rn(v0, v1);
        } else if (mode == 2) {
          *(half2*)(hPt + (size_t)z*DD*LL + (size_t)row*LL + n0 + col) = __floats2half2_rn(v0, v1);
        } else {
          if (wn == 0)
            *(float2*)(g_Hg + (size_t)(z*LL + m0 + row)*GG + col) = make_float2(v0, v1);
        }
      }
    }
}

// ---------------- k_S2: S tiles (fp16) + online row stats (max, sumexp incl Hg) ----------------
#define S2_A  0
#define S2_B  36864
#define S2_R1 110592
#define S2_MN 111616
#define S2_MR 112128
#define S2_ZR 112640
#define S2_SI 113152
#define S2_SC 113664
#define SM_S2 114688

__global__ __launch_bounds__(128, 2) void k_S2(const int* __restrict__ mask) {
  extern __shared__ char smem[];
  uint32_t sb = (uint32_t)__cvta_generic_to_shared(smem);
  float* fR1 = (float*)(smem + S2_R1);    // [2][128] reduction scratch
  float* fMN = (float*)(smem + S2_MN);    // [128] new row max
  float* fMR = (float*)(smem + S2_MR);    // [128] running max
  float* fZR = (float*)(smem + S2_ZR);    // [128] running sumexp
  int*   iSI = (int*)(smem + S2_SI);      // [128] row mask
  int*   iSC = (int*)(smem + S2_SC);      // [2][128] col mask
  int tid = threadIdx.x, lane = tid & 31, warp = tid >> 5;
  int wm = warp >> 1, wn = warp & 1;
  int z = blockIdx.z, n = z >> 3;
  int m0 = blockIdx.x * 128;
  const __half* Ap = hP + (size_t)(z*LL + m0)*DD;

  #pragma unroll
  for (int kt=0; kt<2; kt++) load_A<false>(sb + S2_A + kt*TILEB, Ap, DD, kt, tid);
  {
    const __half* Bp = hQz + (size_t)n*LL*DD;
    #pragma unroll
    for (int kt=0; kt<2; kt++) load_B(sb + S2_B + kt*TILEB, Bp, DD, kt, tid);
  }
  asm volatile("cp.async.commit_group;");

  // masks + Hg-based stats init (one row per thread)
  iSI[tid] = mask[n*LL + m0 + tid];
  iSC[tid] = mask[n*LL + tid];
  {
    const float* hr = g_Hg + ((size_t)z*LL + m0 + tid)*GG;
    float m = -3.4e38f;
    for (int g = 0; g < GG; g++) m = fmaxf(m, hr[g]);
    float s = 0.f;
    for (int g = 0; g < GG; g++) s += __expf(hr[g] - m);
    fMR[tid] = m; fZR[tid] = s;
  }
  asm volatile("cp.async.wait_group 0;");
  __syncthreads();

  for (int jb = 0; jb < 8; jb++) {
    if (jb < 7) {
      const __half* Bn = hQz + (size_t)(n*LL + (jb+1)*128)*DD;
      #pragma unroll
      for (int kt=0; kt<2; kt++)
        load_B(sb + S2_B + ((jb+1)&1)*STG2B + kt*TILEB, Bn, DD, kt, tid);
      iSC[((jb+1)&1)*128 + tid] = mask[n*LL + (jb+1)*128 + tid];
    }
    asm volatile("cp.async.commit_group;");
    asm volatile("cp.async.wait_group 1;");
    __syncthreads();                       // S1: B(jb) + scmask visible

    float c[4][8][4];
    #pragma unroll
    for (int i=0;i<4;i++)
      #pragma unroll
      for (int j=0;j<8;j++)
        #pragma unroll
        for (int k=0;k<4;k++) c[i][j][k] = 0.f;
    uint32_t bB = sb + S2_B + (jb&1)*STG2B;
    #pragma unroll
    for (int kt=0; kt<2; kt++)
      mma_step<false>(sb + S2_A + kt*TILEB, bB + kt*TILEB, c, wm, wn, lane);

    // apply mask in place
    bool rv[8];
    #pragma unroll
    for (int mf=0; mf<4; mf++)
      #pragma unroll
      for (int rr=0; rr<2; rr++)
        rv[mf*2+rr] = iSI[wm*64 + mf*16 + (lane>>2) + rr*8] != 0;
    unsigned cvm = 0;
    #pragma unroll
    for (int nb=0; nb<8; nb++)
      #pragma unroll
      for (int q=0; q<2; q++)
        if (iSC[(jb&1)*128 + wn*64 + nb*8 + (lane&3)*2 + q]) cvm |= 1u << (nb*2+q);
    #pragma unroll
    for (int mf=0; mf<4; mf++)
      #pragma unroll
      for (int rr=0; rr<2; rr++)
        #pragma unroll
        for (int nb=0; nb<8; nb++)
          #pragma unroll
          for (int q=0; q<2; q++)
            if (!(rv[mf*2+rr] && ((cvm >> (nb*2+q)) & 1))) c[mf][nb][rr*2+q] = NEGV;

    // phase 1: per-row chunk max
    #pragma unroll
    for (int mf=0; mf<4; mf++)
      #pragma unroll
      for (int rr=0; rr<2; rr++) {
        int row = wm*64 + mf*16 + (lane>>2) + rr*8;
        float lm = -3.4e38f;
        #pragma unroll
        for (int nb=0; nb<8; nb++) {
          lm = fmaxf(lm, c[mf][nb][rr*2]);
          lm = fmaxf(lm, c[mf][nb][rr*2+1]);
        }
        lm = fmaxf(lm, __shfl_xor_sync(0xffffffffu, lm, 1));
        lm = fmaxf(lm, __shfl_xor_sync(0xffffffffu, lm, 2));
        if ((lane & 3) == 0) fR1[wn*128 + row] = lm;
      }
    __syncthreads();
    {
      float mc = fmaxf(fR1[tid], fR1[128 + tid]);
      fMN[tid] = fmaxf(fMR[tid], mc);
    }
    __syncthreads();
    // phase 2: sumexp + store raw fp16 logits
    #pragma unroll
    for (int mf=0; mf<4; mf++)
      #pragma unroll
      for (int rr=0; rr<2; rr++) {
        int row = wm*64 + mf*16 + (lane>>2) + rr*8;
        float mn = fMN[row];
        float ls = 0.f;
        __half* drow = g_Sh + ((size_t)z*LL + m0 + row)*LL + jb*128;
        #pragma unroll
        for (int nb=0; nb<8; nb++) {
          float v0 = c[mf][nb][rr*2], v1 = c[mf][nb][rr*2+1];
          ls += __expf(v0 - mn) + __expf(v1 - mn);
          int col = wn*64 + nb*8 + (lane&3)*2;
          *(half2*)(drow + col) = __floats2half2_rn(v0, v1);
        }
        ls += __shfl_xor_sync(0xffffffffu, ls, 1);
        ls += __shfl_xor_sync(0xffffffffu, ls, 2);
        if ((lane & 3) == 0) fR1[wn*128 + row] = ls;
      }
    __syncthreads();
    {
      float Zc = fR1[tid] + fR1[128 + tid];
      float mo = fMR[tid], mn = fMN[tid];
      fZR[tid] = fZR[tid]*__expf(mo - mn) + Zc;
      fMR[tid] = mn;
    }
    __syncthreads();
  }
  g_stats[(size_t)z*LL + m0 + tid] = make_float2(fMR[tid], 1.0f / fZR[tid]);
}

// ---------------- Qhg = exp(Hg - m) * invZ ----------------
__global__ void k_qhg() {
  int idx = blockIdx.x*256 + threadIdx.x;   // NZ*LL*GG = 2M
  int r = idx >> 6;
  float2 st = g_stats[r];
  hHg[idx] = __float2half(__expf(g_Hg[idx] - st.x) * st.y);
}

// ---------------- fused msg_i + msg_j + msg_g with on-the-fly Q ----------------
__global__ __launch_bounds__(128, 2) void k_msg2() {
  extern __shared__ char smem[];
  uint32_t sb = (uint32_t)__cvta_generic_to_shared(smem);
  int tid = threadIdx.x, lane = tid & 31, warp = tid >> 5;
  int wm = warp >> 1, wn = warp & 1;
  int z = blockIdx.z, n = z >> 3, h = z & 7;
  int m0 = blockIdx.x * 128;
  float2* fst = (float2*)(smem + MSG_ST);
  #pragma unroll
  for (int k = 0; k < 8; k++) fst[k*128 + tid] = g_stats[(size_t)z*LL + k*128 + tid];
  __syncthreads();

  float c[4][8][4];
  #pragma unroll
  for (int i=0;i<4;i++)
    #pragma unroll
    for (int j=0;j<8;j++)
      #pragma unroll
      for (int k=0;k<4;k++) c[i][j][k] = 0.f;

  // msg_i[i,a]: A = Q(S rows m0..) via exp-transform, B = Ut[a,j]
  gemm2<false,1>(g_Sh + (size_t)z*LL*LL + (size_t)m0*LL, LL,
                 hUt + (size_t)z*DD*LL, LL, LL, c, smem, sb, m0, tid, wm, wn, lane);
  // msg_j[j,b]: A = Q^T via trans path (stats row = i = kt*64+row), B = Pt[b,i]
  gemm2<true,2>(g_Sh + (size_t)z*LL*LL + m0, LL,
                hPt + (size_t)z*DD*LL, LL, LL, c, smem, sb, 0, tid, wm, wn, lane);
  // msg_g[i,a]: A = Qhg (already probabilities), B = Gt[a,g]
  gemm2<false,0>(hHg + (size_t)(z*LL + m0)*GG, GG,
                 hGt + h*DD*GG, GG, GG, c, smem, sb, 0, tid, wm, wn, lane);

  float* Cb = g_FZ + (size_t)(n*LL + m0)*DD;
  #pragma unroll
  for (int mf = 0; mf < 4; mf++)
    #pragma unroll
    for (int rr = 0; rr < 2; rr++) {
      int row = wm*64 + mf*16 + (lane >> 2) + rr*8;
      #pragma unroll
      for (int nb = 0; nb < 8; nb++) {
        int col = wn*64 + nb*8 + (lane & 3)*2;
        atomicAdd(Cb + (size_t)row*DD + col,     c[mf][nb][rr*2]);
        atomicAdd(Cb + (size_t)row*DD + col + 1, c[mf][nb][rr*2+1]);
      }
    }
}

// ---------------- repack weights to fp16 (+ transposes, padding) ----------------
__global__ void k_repack(const float* __restrict__ ternary, const float* __restrict__ glob) {
  int idx = blockIdx.x*256 + threadIdx.x;
  if (idx < DD*DD*HH) {
    int h = idx % HH; int ab = idx / HH; int b = ab % DD; int a = ab / DD;
    __half v = __float2half(ternary[idx]);
    hT [(h*DD + a)*DD + b] = v;
    hTt[(h*DD + b)*DD + a] = v;
  }
  {
    int h = idx / (128*DD); int rem = idx % (128*DD); int g = rem / DD; int a = rem % DD;
    float gv = (g < GG) ? glob[(g*DD + a)*HH + h] : 0.f;
    hG[idx] = __float2half(gv);
    if (g < GG) hGt[(h*DD + a)*GG + g] = __float2half(gv);
  }
}

// ---------------- softmax over D=128 -> hQz ----------------
__global__ void k_softmax_z(const float* __restrict__ x, int use_fz) {
  const float* in = use_fz ? g_FZ : x;
  int row = blockIdx.x; int t = threadIdx.x;
  float v = in[row*DD + t];
  __shared__ float r1[4], r2[4];
  float m = v;
  #pragma unroll
  for (int o=16;o;o>>=1) m = fmaxf(m, __shfl_xor_sync(0xffffffffu, m, o));
  if ((t&31)==0) r1[t>>5] = m;
  __syncthreads();
  m = fmaxf(fmaxf(r1[0],r1[1]), fmaxf(r1[2],r1[3]));
  float e = __expf(v - m);
  float s = e;
  #pragma unroll
  for (int o=16;o;o>>=1) s += __shfl_xor_sync(0xffffffffu, s, o);
  if ((t&31)==0) r2[t>>5] = s;
  __syncthreads();
  s = r2[0]+r2[1]+r2[2]+r2[3];
  hQz[row*DD + t] = __float2half(e * (1.0f/s));
}

// ---------------- F_Z = x ----------------
__global__ void k_init_fz(const float* __restrict__ x) {
  int i = blockIdx.x*256 + threadIdx.x;
  g_FZ[i] = x[i];
}

// ---------------- output masking ----------------
__global__ void k_out(const int* __restrict__ mask, float* __restrict__ out) {
  int idx = blockIdx.x*256 + threadIdx.x;
  int ni = idx >> 7;
  out[idx] = mask[ni] ? g_FZ[idx] : 0.f;
}

// ---------------- launch ----------------
extern "C" void kernel_launch(void* const* d_in, const int* in_sizes, int n_in,
                              void* d_out, int out_size) {
  const float* x       = (const float*)d_in[0];
  const int*   mask    = (const int*)  d_in[1];
  const float* ternary = (const float*)d_in[2];
  const float* glob    = (const float*)d_in[3];
  float* out = (float*)d_out;

  cudaFuncSetAttribute(k_proj, cudaFuncAttributeMaxDynamicSharedMemorySize, SMEMB);
  cudaFuncSetAttribute(k_S2,   cudaFuncAttributeMaxDynamicSharedMemorySize, SM_S2);
  cudaFuncSetAttribute(k_msg2, cudaFuncAttributeMaxDynamicSharedMemorySize, SM_MSG);

  k_repack<<<512,256>>>(ternary, glob);
  k_softmax_z<<<BB*LL, 128>>>(x, 0);

  for (int it = 0; it < NITER; it++) {
    k_proj<<<dim3(8,4,NZ),128,SMEMB>>>();        // P, Ut, Pt, Hg logits
    k_S2  <<<dim3(8,1,NZ),128,SM_S2>>>(mask);    // S fp16 + row stats
    k_qhg <<<(NZ*LL*GG)/256,256>>>();            // Qhg fp16
    k_init_fz<<<(BB*LL*DD)/256,256>>>(x);        // F_Z = x
    k_msg2<<<dim3(8,1,NZ),128,SM_MSG>>>();       // F_Z += msg_i + msg_j + msg_g
    if (it < NITER-1) k_softmax_z<<<BB*LL, 128>>>(x, 1);
  }
  k_out<<<(BB*LL*DD)/256,256>>>(mask, out);
}

// round 11
// speedup vs baseline: 1.6151x; 1.6151x over previous
#include <cuda_runtime.h>
#include <cuda_fp16.h>
#include <cstdint>

#define BB 4
#define LL 1024
#define DD 128
#define HH 8
#define GG 64
#define NEGV -1000000000.0f
#define NITER 4
#define NZ (BB*HH)

// ---------------- scratch (static device arrays; no allocations) ----------------
__device__ float g_FZ[BB*LL*DD];
__device__ __half g_Sh[(size_t)NZ*LL*LL];         // fp16 pair logits (67MB)
__device__ float g_Hg[NZ*LL*GG];                  // fp32 global logits
__device__ __half hQz[BB*LL*DD];                  // softmax(F_Z)
__device__ __half hP [NZ*LL*DD];                  // P[i,b]
__device__ __half hPt[NZ*DD*LL];                  // P^T[b,i]
__device__ __half hUt[NZ*DD*LL];                  // U^T[a,j]
__device__ __half hQ [(size_t)NZ*LL*LL];          // Qhs probabilities
__device__ __half hHg[NZ*LL*GG];                  // Qhg probabilities
__device__ __half hT [HH*DD*DD];                  // T[h][a][b]
__device__ __half hTt[HH*DD*DD];                  // T[h][b][a]
__device__ __half hG [HH*128*DD];                 // G[h][g][a], g padded to 128
__device__ __half hGt[HH*DD*GG];                  // G^T[h][a][g]

// ---------------- mma.sync GEMM core ----------------
// BM=128, BN=128, BK=64, 128 threads (4 warps as 2m x 2n), warp tile 64x64, 3-stage cp.async.
#define SKA 72                   // A-normal / B smem row stride (halves)
#define SKT 136                  // A-trans smem row stride (halves)
#define TILEB 18432              // max tile bytes (128*72*2)
#define STAGEB (2*TILEB)         // A + B per stage
#define NSTG 3
#define SMEMB (NSTG*STAGEB)      // 110592

template<bool TA>
__device__ __forceinline__ void load_A(uint32_t dst, const __half* A, int lda, int kt, int tid) {
  if (!TA) {
    #pragma unroll
    for (int i = 0; i < 8; i++) {
      int idx = tid + i*128;
      int row = idx >> 3, co = (idx & 7) * 8;
      uint32_t d = dst + (row*SKA + co)*2;
      const __half* s = A + (size_t)row*lda + kt*64 + co;
      asm volatile("cp.async.cg.shared.global [%0], [%1], 16;" :: "r"(d), "l"(s));
    }
  } else {
    #pragma unroll
    for (int i = 0; i < 8; i++) {
      int idx = tid + i*128;
      int row = idx >> 4, co = (idx & 15) * 8;
      uint32_t d = dst + (row*SKT + co)*2;
      const __half* s = A + (size_t)(kt*64 + row)*lda + co;
      asm volatile("cp.async.cg.shared.global [%0], [%1], 16;" :: "r"(d), "l"(s));
    }
  }
}
__device__ __forceinline__ void load_B(uint32_t dst, const __half* B, int ldb, int kt, int tid) {
  #pragma unroll
  for (int i = 0; i < 8; i++) {
    int idx = tid + i*128;
    int row = idx >> 3, co = (idx & 7) * 8;
    uint32_t d = dst + (row*SKA + co)*2;
    const __half* s = B + (size_t)row*ldb + kt*64 + co;
    asm volatile("cp.async.cg.shared.global [%0], [%1], 16;" :: "r"(d), "l"(s));
  }
}

template<bool TA>
__device__ __forceinline__ void gemm_acc(
    const __half* A, int lda, const __half* B, int ldb, int K,
    float (&c)[4][8][4], uint32_t sbase, int tid, int wm, int wn, int lane)
{
  int NK = K >> 6;
  int lr = lane & 7, sel = lane >> 3;
  #pragma unroll
  for (int s = 0; s < NSTG-1; s++) {
    if (s < NK) {
      load_A<TA>(sbase + s*STAGEB, A, lda, s, tid);
      load_B(sbase + s*STAGEB + TILEB, B, ldb, s, tid);
    }
    asm volatile("cp.async.commit_group;");
  }
  for (int kt = 0; kt < NK; kt++) {
    int ps = kt + NSTG - 1;
    if (ps < NK) {
      uint32_t sb = sbase + (ps % NSTG)*STAGEB;
      load_A<TA>(sb, A, lda, ps, tid);
      load_B(sb + TILEB, B, ldb, ps, tid);
    }
    asm volatile("cp.async.commit_group;");
    asm volatile("cp.async.wait_group %0;" :: "n"(NSTG-1));
    __syncthreads();
    uint32_t bufA = sbase + (kt % NSTG)*STAGEB;
    uint32_t bufB = bufA + TILEB;
    #pragma unroll
    for (int kb = 0; kb < 4; kb++) {
      uint32_t afr[4][4], bfr[4][4];
      #pragma unroll
      for (int mf = 0; mf < 4; mf++) {
        if (!TA) {
          int row = wm*64 + mf*16 + lr + ((sel & 1) ? 8 : 0);
          int col = kb*16 + ((sel & 2) ? 8 : 0);
          uint32_t ad = bufA + (row*SKA + col)*2;
          asm volatile("ldmatrix.sync.aligned.m8n8.x4.shared.b16 {%0,%1,%2,%3},[%4];"
            : "=r"(afr[mf][0]), "=r"(afr[mf][1]), "=r"(afr[mf][2]), "=r"(afr[mf][3]) : "r"(ad));
        } else {
          int row = kb*16 + lr + ((sel & 2) ? 8 : 0);
          int col = wm*64 + mf*16 + ((sel & 1) ? 8 : 0);
          uint32_t ad = bufA + (row*SKT + col)*2;
          asm volatile("ldmatrix.sync.aligned.m8n8.x4.trans.shared.b16 {%0,%1,%2,%3},[%4];"
            : "=r"(afr[mf][0]), "=r"(afr[mf][1]), "=r"(afr[mf][2]), "=r"(afr[mf][3]) : "r"(ad));
        }
      }
      #pragma unroll
      for (int p = 0; p < 4; p++) {
        int row = wn*64 + p*16 + lr + ((sel & 2) ? 8 : 0);
        int col = kb*16 + ((sel & 1) ? 8 : 0);
        uint32_t bd = bufB + (row*SKA + col)*2;
        asm volatile("ldmatrix.sync.aligned.m8n8.x4.shared.b16 {%0,%1,%2,%3},[%4];"
          : "=r"(bfr[p][0]), "=r"(bfr[p][1]), "=r"(bfr[p][2]), "=r"(bfr[p][3]) : "r"(bd));
      }
      #pragma unroll
      for (int mf = 0; mf < 4; mf++)
        #pragma unroll
        for (int nb = 0; nb < 8; nb++) {
          asm volatile("mma.sync.aligned.m16n8k16.row.col.f32.f16.f16.f32 "
            "{%0,%1,%2,%3},{%4,%5,%6,%7},{%8,%9},{%0,%1,%2,%3};"
            : "+f"(c[mf][nb][0]), "+f"(c[mf][nb][1]), "+f"(c[mf][nb][2]), "+f"(c[mf][nb][3])
            : "r"(afr[mf][0]), "r"(afr[mf][1]), "r"(afr[mf][2]), "r"(afr[mf][3]),
              "r"(bfr[nb>>1][(nb&1)*2]), "r"(bfr[nb>>1][(nb&1)*2+1]));
        }
    }
    __syncthreads();
  }
}

// ---------------- merged projection kernel: mode = blockIdx.y ----------------
// 0: P[i,b]=Qz@T   1: Ut[a,j]=T@Qz^T   2: Pt[b,i]=Tt@Qz^T   3: Hg[i,g]=Qz@G^T
__global__ __launch_bounds__(128, 2) void k_proj() {
  extern __shared__ char smem[];
  uint32_t sbase = (uint32_t)__cvta_generic_to_shared(smem);
  int tid = threadIdx.x, lane = tid & 31, warp = tid >> 5;
  int wm = warp >> 1, wn = warp & 1;
  int mode = blockIdx.y;
  int z = blockIdx.z, n = z >> 3, h = z & 7;
  int m0 = 0, n0 = 0;
  const __half *A, *B;
  if (mode == 0) {
    m0 = blockIdx.x * 128;
    A = hQz + (size_t)(n*LL + m0)*DD;
    B = hTt + h*DD*DD;
  } else if (mode == 1) {
    n0 = blockIdx.x * 128;
    A = hT + h*DD*DD;
    B = hQz + (size_t)(n*LL + n0)*DD;
  } else if (mode == 2) {
    n0 = blockIdx.x * 128;
    A = hTt + h*DD*DD;
    B = hQz + (size_t)(n*LL + n0)*DD;
  } else {
    m0 = blockIdx.x * 128;
    A = hQz + (size_t)(n*LL + m0)*DD;
    B = hG + h*128*DD;
  }
  float c[4][8][4];
  #pragma unroll
  for (int i=0;i<4;i++)
    #pragma unroll
    for (int j=0;j<8;j++)
      #pragma unroll
      for (int k=0;k<4;k++) c[i][j][k] = 0.f;

  gemm_acc<false>(A, DD, B, DD, DD, c, sbase, tid, wm, wn, lane);

  #pragma unroll
  for (int mf = 0; mf < 4; mf++)
    #pragma unroll
    for (int rr = 0; rr < 2; rr++) {
      int row = wm*64 + mf*16 + (lane >> 2) + rr*8;
      #pragma unroll
      for (int nb = 0; nb < 8; nb++) {
        int col = wn*64 + nb*8 + (lane & 3)*2;
        float v0 = c[mf][nb][rr*2], v1 = c[mf][nb][rr*2+1];
        if (mode == 0) {
          *(half2*)(hP + (size_t)(z*LL + m0 + row)*DD + col) = __floats2half2_rn(v0, v1);
        } else if (mode == 1) {
          *(half2*)(hUt + (size_t)z*DD*LL + (size_t)row*LL + n0 + col) = __floats2half2_rn(v0, v1);
        } else if (mode == 2) {
          *(half2*)(hPt + (size_t)z*DD*LL + (size_t)row*LL + n0 + col) = __floats2half2_rn(v0, v1);
        } else {
          if (wn == 0)
            *(float2*)(g_Hg + (size_t)(z*LL + m0 + row)*GG + col) = make_float2(v0, v1);
        }
      }
    }
}

// ---------------- S[i,j] = P @ Qz^T  (stored fp16) ----------------
__global__ __launch_bounds__(128, 2) void k_S() {
  extern __shared__ char smem[];
  uint32_t sbase = (uint32_t)__cvta_generic_to_shared(smem);
  int tid = threadIdx.x, lane = tid & 31, warp = tid >> 5;
  int wm = warp >> 1, wn = warp & 1;
  int z = blockIdx.z, n = z >> 3;
  int m0 = blockIdx.x * 128, n0 = blockIdx.y * 128;
  const __half* A = hP + (size_t)(z*LL + m0)*DD;
  const __half* B = hQz + (size_t)(n*LL + n0)*DD;
  float c[4][8][4];
  #pragma unroll
  for (int i=0;i<4;i++)
    #pragma unroll
    for (int j=0;j<8;j++)
      #pragma unroll
      for (int k=0;k<4;k++) c[i][j][k] = 0.f;

  gemm_acc<false>(A, DD, B, DD, DD, c, sbase, tid, wm, wn, lane);

  #pragma unroll
  for (int mf = 0; mf < 4; mf++)
    #pragma unroll
    for (int rr = 0; rr < 2; rr++) {
      int row = wm*64 + mf*16 + (lane >> 2) + rr*8;
      #pragma unroll
      for (int nb = 0; nb < 8; nb++) {
        int col = wn*64 + nb*8 + (lane & 3)*2;
        *(half2*)(g_Sh + (size_t)(z*LL + m0 + row)*LL + n0 + col) =
            __floats2half2_rn(c[mf][nb][rr*2], c[mf][nb][rr*2+1]);
      }
    }
}

// ---------------- fused msg_i + msg_j + msg_g per head, atomic into F_Z ----------------
__global__ __launch_bounds__(128, 2) void k_msg() {
  extern __shared__ char smem[];
  uint32_t sbase = (uint32_t)__cvta_generic_to_shared(smem);
  int tid = threadIdx.x, lane = tid & 31, warp = tid >> 5;
  int wm = warp >> 1, wn = warp & 1;
  int z = blockIdx.z, n = z >> 3, h = z & 7;
  int m0 = blockIdx.x * 128;
  float c[4][8][4];
  #pragma unroll
  for (int i=0;i<4;i++)
    #pragma unroll
    for (int j=0;j<8;j++)
      #pragma unroll
      for (int k=0;k<4;k++) c[i][j][k] = 0.f;

  // msg_i[i,a]: A = Q[i,j] rows m0.., B = Ut[a,j]
  gemm_acc<false>(hQ + (size_t)z*LL*LL + (size_t)m0*LL, LL,
                  hUt + (size_t)z*DD*LL, LL, LL, c, sbase, tid, wm, wn, lane);
  // msg_j[j,b]: A = Q^T via ldmatrix.trans (tile = Q rows k, cols m0..), B = Pt[b,i]
  gemm_acc<true>(hQ + (size_t)z*LL*LL + m0, LL,
                 hPt + (size_t)z*DD*LL, LL, LL, c, sbase, tid, wm, wn, lane);
  // msg_g[i,a]: A = Qhg[i,g], B = Gt[a,g]
  gemm_acc<false>(hHg + (size_t)(z*LL + m0)*GG, GG,
                  hGt + h*DD*GG, GG, GG, c, sbase, tid, wm, wn, lane);

  float* Cb = g_FZ + (size_t)(n*LL + m0)*DD;
  #pragma unroll
  for (int mf = 0; mf < 4; mf++)
    #pragma unroll
    for (int rr = 0; rr < 2; rr++) {
      int row = wm*64 + mf*16 + (lane >> 2) + rr*8;
      #pragma unroll
      for (int nb = 0; nb < 8; nb++) {
        int col = wn*64 + nb*8 + (lane & 3)*2;
        atomicAdd(Cb + (size_t)row*DD + col,     c[mf][nb][rr*2]);
        atomicAdd(Cb + (size_t)row*DD + col + 1, c[mf][nb][rr*2+1]);
      }
    }
}

// ---------------- repack weights to fp16 (+ transposes, padding) ----------------
__global__ void k_repack(const float* __restrict__ ternary, const float* __restrict__ glob) {
  int idx = blockIdx.x*256 + threadIdx.x;     // 0..131071
  if (idx < DD*DD*HH) {
    int h = idx % HH; int ab = idx / HH; int b = ab % DD; int a = ab / DD;
    __half v = __float2half(ternary[idx]);
    hT [(h*DD + a)*DD + b] = v;
    hTt[(h*DD + b)*DD + a] = v;
  }
  {
    int h = idx / (128*DD); int rem = idx % (128*DD); int g = rem / DD; int a = rem % DD;
    float gv = (g < GG) ? glob[(g*DD + a)*HH + h] : 0.f;
    hG[idx] = __float2half(gv);
    if (g < GG) hGt[(h*DD + a)*GG + g] = __float2half(gv);
  }
}

// ---------------- softmax over D=128 -> hQz ----------------
__global__ void k_softmax_z(const float* __restrict__ x, int use_fz) {
  const float* in = use_fz ? g_FZ : x;
  int row = blockIdx.x; int t = threadIdx.x;  // 128
  float v = in[row*DD + t];
  __shared__ float r1[4], r2[4];
  float m = v;
  #pragma unroll
  for (int o=16;o;o>>=1) m = fmaxf(m, __shfl_xor_sync(0xffffffffu, m, o));
  if ((t&31)==0) r1[t>>5] = m;
  __syncthreads();
  m = fmaxf(fmaxf(r1[0],r1[1]), fmaxf(r1[2],r1[3]));
  float e = __expf(v - m);
  float s = e;
  #pragma unroll
  for (int o=16;o;o>>=1) s += __shfl_xor_sync(0xffffffffu, s, o);
  if ((t&31)==0) r2[t>>5] = s;
  __syncthreads();
  s = r2[0]+r2[1]+r2[2]+r2[3];
  hQz[row*DD + t] = __float2half(e * (1.0f/s));
}

// ---------------- softmax over concat [S row fp16 (1024) | Hg row (64)] -> hQ, hHg ----------------
__global__ void k_softmax_h(const int* __restrict__ mask) {
  int r = blockIdx.x;                 // z*L + i
  int t = threadIdx.x;                // 256
  const __half* Srow = g_Sh + (size_t)r*LL;
  const float* Hrow = g_Hg + (size_t)r*GG;
  int n = r >> 13;
  int i = r & (LL-1);
  const int* mrow = mask + n*LL;
  int mi = mrow[i];
  // contiguous 4 halves per thread
  float v[4];
  {
    uint2 raw = *(const uint2*)(Srow + t*4);
    __half2* hp = (__half2*)&raw;
    float2 f0 = __half22float2(hp[0]);
    float2 f1 = __half22float2(hp[1]);
    v[0]=f0.x; v[1]=f0.y; v[2]=f1.x; v[3]=f1.y;
  }
  int4 mc = *(const int4*)(mrow + t*4);
  int mm[4] = {mc.x, mc.y, mc.z, mc.w};
  float lm = -3.4e38f;
  #pragma unroll
  for (int s=0;s<4;s++) {
    if (!(mi && mm[s])) v[s] = NEGV;
    lm = fmaxf(lm, v[s]);
  }
  float hgv = 0.f;
  if (t < GG) { hgv = Hrow[t]; lm = fmaxf(lm, hgv); }
  __shared__ float sm[8], ss[8];
  float w = lm;
  #pragma unroll
  for (int o=16;o;o>>=1) w = fmaxf(w, __shfl_xor_sync(0xffffffffu, w, o));
  if ((t&31)==0) sm[t>>5] = w;
  __syncthreads();
  float m = sm[0];
  #pragma unroll
  for (int q=1;q<8;q++) m = fmaxf(m, sm[q]);
  float sum = 0.f;
  #pragma unroll
  for (int s=0;s<4;s++) { v[s] = __expf(v[s]-m); sum += v[s]; }
  if (t < GG) { hgv = __expf(hgv-m); sum += hgv; }
  #pragma unroll
  for (int o=16;o;o>>=1) sum += __shfl_xor_sync(0xffffffffu, sum, o);
  if ((t&31)==0) ss[t>>5] = sum;
  __syncthreads();
  float tot = 0.f;
  #pragma unroll
  for (int q=0;q<8;q++) tot += ss[q];
  float inv = 1.0f/tot;
  __half* Qrow = hQ + (size_t)r*LL;
  {
    uint2 outp;
    __half2* op = (__half2*)&outp;
    op[0] = __floats2half2_rn(v[0]*inv, v[1]*inv);
    op[1] = __floats2half2_rn(v[2]*inv, v[3]*inv);
    *(uint2*)(Qrow + t*4) = outp;
  }
  if (t < GG) hHg[(size_t)r*GG + t] = __float2half(hgv*inv);
}

// ---------------- F_Z = x ----------------
__global__ void k_init_fz(const float* __restrict__ x) {
  int i = blockIdx.x*256 + threadIdx.x;
  g_FZ[i] = x[i];
}

// ---------------- output masking ----------------
__global__ void k_out(const int* __restrict__ mask, float* __restrict__ out) {
  int idx = blockIdx.x*256 + threadIdx.x;
  int ni = idx >> 7;
  out[idx] = mask[ni] ? g_FZ[idx] : 0.f;
}

// ---------------- launch ----------------
extern "C" void kernel_launch(void* const* d_in, const int* in_sizes, int n_in,
                              void* d_out, int out_size) {
  const float* x       = (const float*)d_in[0];
  const int*   mask    = (const int*)  d_in[1];
  const float* ternary = (const float*)d_in[2];
  const float* glob    = (const float*)d_in[3];
  float* out = (float*)d_out;

  cudaFuncSetAttribute(k_proj, cudaFuncAttributeMaxDynamicSharedMemorySize, SMEMB);
  cudaFuncSetAttribute(k_S,    cudaFuncAttributeMaxDynamicSharedMemorySize, SMEMB);
  cudaFuncSetAttribute(k_msg,  cudaFuncAttributeMaxDynamicSharedMemorySize, SMEMB);

  k_repack<<<512,256>>>(ternary, glob);
  k_softmax_z<<<BB*LL, 128>>>(x, 0);

  for (int it = 0; it < NITER; it++) {
    k_proj<<<dim3(8,4,NZ),128,SMEMB>>>();     // P, Ut, Pt, Hg logits
    k_S   <<<dim3(8,8,NZ),128,SMEMB>>>();     // S logits (fp16)
    k_softmax_h<<<NZ*LL, 256>>>(mask);        // -> hQ, hHg
    k_init_fz<<<(BB*LL*DD)/256,256>>>(x);     // F_Z = x
    k_msg <<<dim3(8,1,NZ),128,SMEMB>>>();     // F_Z += msg_i + msg_j + msg_g
    if (it < NITER-1) k_softmax_z<<<BB*LL, 128>>>(x, 1);
  }
  k_out<<<(BB*LL*DD)/256,256>>>(mask, out);
}

// round 16
// speedup vs baseline: 1.6261x; 1.0068x over previous
#include <cuda_runtime.h>
#include <cuda_fp16.h>
#include <cstdint>

#define BB 4
#define LL 1024
#define DD 128
#define HH 8
#define GG 64
#define NEGV -1000000000.0f
#define NITER 4
#define NZ (BB*HH)

// ---------------- scratch (static device arrays; no allocations) ----------------
__device__ float g_FZ[BB*LL*DD];
__device__ __half g_Sh[(size_t)NZ*LL*LL];         // fp16 pair logits (67MB)
__device__ float g_Hg[NZ*LL*GG];                  // fp32 global logits
__device__ __half hQz[BB*LL*DD];                  // softmax(F_Z)
__device__ __half hP [NZ*LL*DD];                  // P[i,b]
__device__ __half hPt[NZ*DD*LL];                  // P^T[b,i]
__device__ __half hUt[NZ*DD*LL];                  // U^T[a,j]
__device__ __half hQ [(size_t)NZ*LL*LL];          // Qhs probabilities
__device__ __half hHg[NZ*LL*GG];                  // Qhg probabilities
__device__ __half hT [HH*DD*DD];                  // T[h][a][b]
__device__ __half hTt[HH*DD*DD];                  // T[h][b][a]
__device__ __half hG [HH*128*DD];                 // G[h][g][a], g padded to 128
__device__ __half hGt[HH*DD*GG];                  // G^T[h][a][g]

// ---------------- mma.sync GEMM core ----------------
// BM=128, BN=128, BK=64, 128 threads (4 warps as 2m x 2n), warp tile 64x64,
// 3-stage cp.async + double-buffered ldmatrix fragments (LDSM/MMA overlap).
#define SKA 72                   // A-normal / B smem row stride (halves)
#define SKT 136                  // A-trans smem row stride (halves)
#define TILEB 18432              // max tile bytes (128*72*2)
#define STAGEB (2*TILEB)         // A + B per stage
#define NSTG 3
#define SMEMB (NSTG*STAGEB)      // 110592

template<bool TA>
__device__ __forceinline__ void load_A(uint32_t dst, const __half* A, int lda, int kt, int tid) {
  if (!TA) {
    #pragma unroll
    for (int i = 0; i < 8; i++) {
      int idx = tid + i*128;
      int row = idx >> 3, co = (idx & 7) * 8;
      uint32_t d = dst + (row*SKA + co)*2;
      const __half* s = A + (size_t)row*lda + kt*64 + co;
      asm volatile("cp.async.cg.shared.global [%0], [%1], 16;" :: "r"(d), "l"(s));
    }
  } else {
    #pragma unroll
    for (int i = 0; i < 8; i++) {
      int idx = tid + i*128;
      int row = idx >> 4, co = (idx & 15) * 8;
      uint32_t d = dst + (row*SKT + co)*2;
      const __half* s = A + (size_t)(kt*64 + row)*lda + co;
      asm volatile("cp.async.cg.shared.global [%0], [%1], 16;" :: "r"(d), "l"(s));
    }
  }
}
__device__ __forceinline__ void load_B(uint32_t dst, const __half* B, int ldb, int kt, int tid) {
  #pragma unroll
  for (int i = 0; i < 8; i++) {
    int idx = tid + i*128;
    int row = idx >> 3, co = (idx & 7) * 8;
    uint32_t d = dst + (row*SKA + co)*2;
    const __half* s = B + (size_t)row*ldb + kt*64 + co;
    asm volatile("cp.async.cg.shared.global [%0], [%1], 16;" :: "r"(d), "l"(s));
  }
}

// ---- fragment loaders + mma (warp tile 64x64) ----
template<bool TA>
__device__ __forceinline__ void ld_afr(uint32_t (&afr)[4][4], uint32_t bufA, int kb, int wm, int lane) {
  int lr = lane & 7, sel = lane >> 3;
  #pragma unroll
  for (int mf = 0; mf < 4; mf++) {
    if (!TA) {
      int row = wm*64 + mf*16 + lr + ((sel & 1) ? 8 : 0);
      int col = kb*16 + ((sel & 2) ? 8 : 0);
      uint32_t ad = bufA + (row*SKA + col)*2;
      asm volatile("ldmatrix.sync.aligned.m8n8.x4.shared.b16 {%0,%1,%2,%3},[%4];"
        : "=r"(afr[mf][0]), "=r"(afr[mf][1]), "=r"(afr[mf][2]), "=r"(afr[mf][3]) : "r"(ad));
    } else {
      int row = kb*16 + lr + ((sel & 2) ? 8 : 0);
      int col = wm*64 + mf*16 + ((sel & 1) ? 8 : 0);
      uint32_t ad = bufA + (row*SKT + col)*2;
      asm volatile("ldmatrix.sync.aligned.m8n8.x4.trans.shared.b16 {%0,%1,%2,%3},[%4];"
        : "=r"(afr[mf][0]), "=r"(afr[mf][1]), "=r"(afr[mf][2]), "=r"(afr[mf][3]) : "r"(ad));
    }
  }
}
__device__ __forceinline__ void ld_bfr(uint32_t (&bfr)[4][4], uint32_t bufB, int kb, int wn, int lane) {
  int lr = lane & 7, sel = lane >> 3;
  #pragma unroll
  for (int p = 0; p < 4; p++) {
    int row = wn*64 + p*16 + lr + ((sel & 2) ? 8 : 0);
    int col = kb*16 + ((sel & 1) ? 8 : 0);
    uint32_t bd = bufB + (row*SKA + col)*2;
    asm volatile("ldmatrix.sync.aligned.m8n8.x4.shared.b16 {%0,%1,%2,%3},[%4];"
      : "=r"(bfr[p][0]), "=r"(bfr[p][1]), "=r"(bfr[p][2]), "=r"(bfr[p][3]) : "r"(bd));
  }
}
__device__ __forceinline__ void do_mma(float (&c)[4][8][4],
    const uint32_t (&afr)[4][4], const uint32_t (&bfr)[4][4]) {
  #pragma unroll
  for (int mf = 0; mf < 4; mf++)
    #pragma unroll
    for (int nb = 0; nb < 8; nb++) {
      asm volatile("mma.sync.aligned.m16n8k16.row.col.f32.f16.f16.f32 "
        "{%0,%1,%2,%3},{%4,%5,%6,%7},{%8,%9},{%0,%1,%2,%3};"
        : "+f"(c[mf][nb][0]), "+f"(c[mf][nb][1]), "+f"(c[mf][nb][2]), "+f"(c[mf][nb][3])
        : "r"(afr[mf][0]), "r"(afr[mf][1]), "r"(afr[mf][2]), "r"(afr[mf][3]),
          "r"(bfr[nb>>1][(nb&1)*2]), "r"(bfr[nb>>1][(nb&1)*2+1]));
    }
}

template<bool TA>
__device__ __forceinline__ void gemm_acc(
    const __half* A, int lda, const __half* B, int ldb, int K,
    float (&c)[4][8][4], uint32_t sbase, int tid, int wm, int wn, int lane)
{
  int NK = K >> 6;
  #pragma unroll
  for (int s = 0; s < NSTG-1; s++) {
    if (s < NK) {
      load_A<TA>(sbase + s*STAGEB, A, lda, s, tid);
      load_B(sbase + s*STAGEB + TILEB, B, ldb, s, tid);
    }
    asm volatile("cp.async.commit_group;");
  }
  for (int kt = 0; kt < NK; kt++) {
    int ps = kt + NSTG - 1;
    if (ps < NK) {
      uint32_t sb = sbase + (ps % NSTG)*STAGEB;
      load_A<TA>(sb, A, lda, ps, tid);
      load_B(sb + TILEB, B, ldb, ps, tid);
    }
    asm volatile("cp.async.commit_group;");
    asm volatile("cp.async.wait_group %0;" :: "n"(NSTG-1));
    __syncthreads();
    uint32_t bufA = sbase + (kt % NSTG)*STAGEB;
    uint32_t bufB = bufA + TILEB;
    // double-buffered fragments: issue LDSM for kb+1 before MMA of kb
    uint32_t afr[2][4][4], bfr[2][4][4];
    ld_afr<TA>(afr[0], bufA, 0, wm, lane);
    ld_bfr(bfr[0], bufB, 0, wn, lane);
    #pragma unroll
    for (int kb = 0; kb < 4; kb++) {
      int cur = kb & 1;
      if (kb < 3) {
        ld_afr<TA>(afr[cur^1], bufA, kb+1, wm, lane);
        ld_bfr(bfr[cur^1], bufB, kb+1, wn, lane);
      }
      do_mma(c, afr[cur], bfr[cur]);
    }
    __syncthreads();
  }
}

// ---------------- merged projection kernel: mode = blockIdx.y ----------------
// 0: P[i,b]=Qz@T   1: Ut[a,j]=T@Qz^T   2: Pt[b,i]=Tt@Qz^T   3: Hg[i,g]=Qz@G^T
__global__ __launch_bounds__(128, 2) void k_proj() {
  extern __shared__ char smem[];
  uint32_t sbase = (uint32_t)__cvta_generic_to_shared(smem);
  int tid = threadIdx.x, lane = tid & 31, warp = tid >> 5;
  int wm = warp >> 1, wn = warp & 1;
  int mode = blockIdx.y;
  int z = blockIdx.z, n = z >> 3, h = z & 7;
  int m0 = 0, n0 = 0;
  const __half *A, *B;
  if (mode == 0) {
    m0 = blockIdx.x * 128;
    A = hQz + (size_t)(n*LL + m0)*DD;
    B = hTt + h*DD*DD;
  } else if (mode == 1) {
    n0 = blockIdx.x * 128;
    A = hT + h*DD*DD;
    B = hQz + (size_t)(n*LL + n0)*DD;
  } else if (mode == 2) {
    n0 = blockIdx.x * 128;
    A = hTt + h*DD*DD;
    B = hQz + (size_t)(n*LL + n0)*DD;
  } else {
    m0 = blockIdx.x * 128;
    A = hQz + (size_t)(n*LL + m0)*DD;
    B = hG + h*128*DD;
  }
  float c[4][8][4];
  #pragma unroll
  for (int i=0;i<4;i++)
    #pragma unroll
    for (int j=0;j<8;j++)
      #pragma unroll
      for (int k=0;k<4;k++) c[i][j][k] = 0.f;

  gemm_acc<false>(A, DD, B, DD, DD, c, sbase, tid, wm, wn, lane);

  #pragma unroll
  for (int mf = 0; mf < 4; mf++)
    #pragma unroll
    for (int rr = 0; rr < 2; rr++) {
      int row = wm*64 + mf*16 + (lane >> 2) + rr*8;
      #pragma unroll
      for (int nb = 0; nb < 8; nb++) {
        int col = wn*64 + nb*8 + (lane & 3)*2;
        float v0 = c[mf][nb][rr*2], v1 = c[mf][nb][rr*2+1];
        if (mode == 0) {
          *(half2*)(hP + (size_t)(z*LL + m0 + row)*DD + col) = __floats2half2_rn(v0, v1);
        } else if (mode == 1) {
          *(half2*)(hUt + (size_t)z*DD*LL + (size_t)row*LL + n0 + col) = __floats2half2_rn(v0, v1);
        } else if (mode == 2) {
          *(half2*)(hPt + (size_t)z*DD*LL + (size_t)row*LL + n0 + col) = __floats2half2_rn(v0, v1);
        } else {
          if (wn == 0)
            *(float2*)(g_Hg + (size_t)(z*LL + m0 + row)*GG + col) = make_float2(v0, v1);
        }
      }
    }
}

// ---------------- S[i,j] = P @ Qz^T  (stored fp16) ----------------
__global__ __launch_bounds__(128, 2) void k_S() {
  extern __shared__ char smem[];
  uint32_t sbase = (uint32_t)__cvta_generic_to_shared(smem);
  int tid = threadIdx.x, lane = tid & 31, warp = tid >> 5;
  int wm = warp >> 1, wn = warp & 1;
  int z = blockIdx.z, n = z >> 3;
  int m0 = blockIdx.x * 128, n0 = blockIdx.y * 128;
  const __half* A = hP + (size_t)(z*LL + m0)*DD;
  const __half* B = hQz + (size_t)(n*LL + n0)*DD;
  float c[4][8][4];
  #pragma unroll
  for (int i=0;i<4;i++)
    #pragma unroll
    for (int j=0;j<8;j++)
      #pragma unroll
      for (int k=0;k<4;k++) c[i][j][k] = 0.f;

  gemm_acc<false>(A, DD, B, DD, DD, c, sbase, tid, wm, wn, lane);

  #pragma unroll
  for (int mf = 0; mf < 4; mf++)
    #pragma unroll
    for (int rr = 0; rr < 2; rr++) {
      int row = wm*64 + mf*16 + (lane >> 2) + rr*8;
      #pragma unroll
      for (int nb = 0; nb < 8; nb++) {
        int col = wn*64 + nb*8 + (lane & 3)*2;
        *(half2*)(g_Sh + (size_t)(z*LL + m0 + row)*LL + n0 + col) =
            __floats2half2_rn(c[mf][nb][rr*2], c[mf][nb][rr*2+1]);
      }
    }
}

// ---------------- fused msg_i + msg_j + msg_g per head, atomic into F_Z ----------------
__global__ __launch_bounds__(128, 2) void k_msg() {
  extern __shared__ char smem[];
  uint32_t sbase = (uint32_t)__cvta_generic_to_shared(smem);
  int tid = threadIdx.x, lane = tid & 31, warp = tid >> 5;
  int wm = warp >> 1, wn = warp & 1;
  int z = blockIdx.z, n = z >> 3, h = z & 7;
  int m0 = blockIdx.x * 128;
  float c[4][8][4];
  #pragma unroll
  for (int i=0;i<4;i++)
    #pragma unroll
    for (int j=0;j<8;j++)
      #pragma unroll
      for (int k=0;k<4;k++) c[i][j][k] = 0.f;

  // msg_i[i,a]: A = Q[i,j] rows m0.., B = Ut[a,j]
  gemm_acc<false>(hQ + (size_t)z*LL*LL + (size_t)m0*LL, LL,
                  hUt + (size_t)z*DD*LL, LL, LL, c, sbase, tid, wm, wn, lane);
  // msg_j[j,b]: A = Q^T via ldmatrix.trans (tile = Q rows k, cols m0..), B = Pt[b,i]
  gemm_acc<true>(hQ + (size_t)z*LL*LL + m0, LL,
                 hPt + (size_t)z*DD*LL, LL, LL, c, sbase, tid, wm, wn, lane);
  // msg_g[i,a]: A = Qhg[i,g], B = Gt[a,g]
  gemm_acc<false>(hHg + (size_t)(z*LL + m0)*GG, GG,
                  hGt + h*DD*GG, GG, GG, c, sbase, tid, wm, wn, lane);

  float* Cb = g_FZ + (size_t)(n*LL + m0)*DD;
  #pragma unroll
  for (int mf = 0; mf < 4; mf++)
    #pragma unroll
    for (int rr = 0; rr < 2; rr++) {
      int row = wm*64 + mf*16 + (lane >> 2) + rr*8;
      #pragma unroll
      for (int nb = 0; nb < 8; nb++) {
        int col = wn*64 + nb*8 + (lane & 3)*2;
        atomicAdd(Cb + (size_t)row*DD + col,     c[mf][nb][rr*2]);
        atomicAdd(Cb + (size_t)row*DD + col + 1, c[mf][nb][rr*2+1]);
      }
    }
}

// ---------------- repack weights to fp16 (+ transposes, padding) ----------------
__global__ void k_repack(const float* __restrict__ ternary, const float* __restrict__ glob) {
  int idx = blockIdx.x*256 + threadIdx.x;     // 0..131071
  if (idx < DD*DD*HH) {
    int h = idx % HH; int ab = idx / HH; int b = ab % DD; int a = ab / DD;
    __half v = __float2half(ternary[idx]);
    hT [(h*DD + a)*DD + b] = v;
    hTt[(h*DD + b)*DD + a] = v;
  }
  {
    int h = idx / (128*DD); int rem = idx % (128*DD); int g = rem / DD; int a = rem % DD;
    float gv = (g < GG) ? glob[(g*DD + a)*HH + h] : 0.f;
    hG[idx] = __float2half(gv);
    if (g < GG) hGt[(h*DD + a)*GG + g] = __float2half(gv);
  }
}

// ---------------- softmax over D=128 -> hQz ----------------
__global__ void k_softmax_z(const float* __restrict__ x, int use_fz) {
  const float* in = use_fz ? g_FZ : x;
  int row = blockIdx.x; int t = threadIdx.x;  // 128
  float v = in[row*DD + t];
  __shared__ float r1[4], r2[4];
  float m = v;
  #pragma unroll
  for (int o=16;o;o>>=1) m = fmaxf(m, __shfl_xor_sync(0xffffffffu, m, o));
  if ((t&31)==0) r1[t>>5] = m;
  __syncthreads();
  m = fmaxf(fmaxf(r1[0],r1[1]), fmaxf(r1[2],r1[3]));
  float e = __expf(v - m);
  float s = e;
  #pragma unroll
  for (int o=16;o;o>>=1) s += __shfl_xor_sync(0xffffffffu, s, o);
  if ((t&31)==0) r2[t>>5] = s;
  __syncthreads();
  s = r2[0]+r2[1]+r2[2]+r2[3];
  hQz[row*DD + t] = __float2half(e * (1.0f/s));
}

// ---------------- softmax over concat [S row fp16 (1024) | Hg row (64)] -> hQ, hHg ----------------
__global__ void k_softmax_h(const int* __restrict__ mask) {
  int r = blockIdx.x;                 // z*L + i
  int t = threadIdx.x;                // 256
  const __half* Srow = g_Sh + (size_t)r*LL;
  const float* Hrow = g_Hg + (size_t)r*GG;
  int n = r >> 13;
  int i = r & (LL-1);
  const int* mrow = mask + n*LL;
  int mi = mrow[i];
  // contiguous 4 halves per thread
  float v[4];
  {
    uint2 raw = *(const uint2*)(Srow + t*4);
    __half2* hp = (__half2*)&raw;
    float2 f0 = __half22float2(hp[0]);
    float2 f1 = __half22float2(hp[1]);
    v[0]=f0.x; v[1]=f0.y; v[2]=f1.x; v[3]=f1.y;
  }
  int4 mc = *(const int4*)(mrow + t*4);
  int mm[4] = {mc.x, mc.y, mc.z, mc.w};
  float lm = -3.4e38f;
  #pragma unroll
  for (int s=0;s<4;s++) {
    if (!(mi && mm[s])) v[s] = NEGV;
    lm = fmaxf(lm, v[s]);
  }
  float hgv = 0.f;
  if (t < GG) { hgv = Hrow[t]; lm = fmaxf(lm, hgv); }
  __shared__ float sm[8], ss[8];
  float w = lm;
  #pragma unroll
  for (int o=16;o;o>>=1) w = fmaxf(w, __shfl_xor_sync(0xffffffffu, w, o));
  if ((t&31)==0) sm[t>>5] = w;
  __syncthreads();
  float m = sm[0];
  #pragma unroll
  for (int q=1;q<8;q++) m = fmaxf(m, sm[q]);
  float sum = 0.f;
  #pragma unroll
  for (int s=0;s<4;s++) { v[s] = __expf(v[s]-m); sum += v[s]; }
  if (t < GG) { hgv = __expf(hgv-m); sum += hgv; }
  #pragma unroll
  for (int o=16;o;o>>=1) sum += __shfl_xor_sync(0xffffffffu, sum, o);
  if ((t&31)==0) ss[t>>5] = sum;
  __syncthreads();
  float tot = 0.f;
  #pragma unroll
  for (int q=0;q<8;q++) tot += ss[q];
  float inv = 1.0f/tot;
  __half* Qrow = hQ + (size_t)r*LL;
  {
    uint2 outp;
    __half2* op = (__half2*)&outp;
    op[0] = __floats2half2_rn(v[0]*inv, v[1]*inv);
    op[1] = __floats2half2_rn(v[2]*inv, v[3]*inv);
    *(uint2*)(Qrow + t*4) = outp;
  }
  if (t < GG) hHg[(size_t)r*GG + t] = __float2half(hgv*inv);
}

// ---------------- F_Z = x ----------------
__global__ void k_init_fz(const float* __restrict__ x) {
  int i = blockIdx.x*256 + threadIdx.x;
  g_FZ[i] = x[i];
}

// ---------------- output masking ----------------
__global__ void k_out(const int* __restrict__ mask, float* __restrict__ out) {
  int idx = blockIdx.x*256 + threadIdx.x;
  int ni = idx >> 7;
  out[idx] = mask[ni] ? g_FZ[idx] : 0.f;
}

// ---------------- launch ----------------
extern "C" void kernel_launch(void* const* d_in, const int* in_sizes, int n_in,
                              void* d_out, int out_size) {
  const float* x       = (const float*)d_in[0];
  const int*   mask    = (const int*)  d_in[1];
  const float* ternary = (const float*)d_in[2];
  const float* glob    = (const float*)d_in[3];
  float* out = (float*)d_out;

  cudaFuncSetAttribute(k_proj, cudaFuncAttributeMaxDynamicSharedMemorySize, SMEMB);
  cudaFuncSetAttribute(k_S,    cudaFuncAttributeMaxDynamicSharedMemorySize, SMEMB);
  cudaFuncSetAttribute(k_msg,  cudaFuncAttributeMaxDynamicSharedMemorySize, SMEMB);

  k_repack<<<512,256>>>(ternary, glob);
  k_softmax_z<<<BB*LL, 128>>>(x, 0);

  for (int it = 0; it < NITER; it++) {
    k_proj<<<dim3(8,4,NZ),128,SMEMB>>>();     // P, Ut, Pt, Hg logits
    k_S   <<<dim3(8,8,NZ),128,SMEMB>>>();     // S logits (fp16)
    k_softmax_h<<<NZ*LL, 256>>>(mask);        // -> hQ, hHg
    k_init_fz<<<(BB*LL*DD)/256,256>>>(x);     // F_Z = x
    k_msg <<<dim3(8,1,NZ),128,SMEMB>>>();     // F_Z += msg_i + msg_j + msg_g
    if (it < NITER-1) k_softmax_z<<<BB*LL, 128>>>(x, 1);
  }
  k_out<<<(BB*LL*DD)/256,256>>>(mask, out);
}

// round 17
// speedup vs baseline: 1.6362x; 1.0062x over previous
#include <cuda_runtime.h>
#include <cuda_fp16.h>
#include <cstdint>

#define BB 4
#define LL 1024
#define DD 128
#define HH 8
#define GG 64
#define NEGV -1000000000.0f
#define NITER 4
#define NZ (BB*HH)

// ---------------- scratch (static device arrays; no allocations) ----------------
__device__ float g_FZ[BB*LL*DD];
__device__ __half g_Sh[(size_t)NZ*LL*LL];         // fp16 pair logits (67MB)
__device__ float g_Hg[NZ*LL*GG];                  // fp32 global logits
__device__ __half hQz[BB*LL*DD];                  // softmax(F_Z)
__device__ __half hP [NZ*LL*DD];                  // P[i,b]
__device__ __half hPt[NZ*DD*LL];                  // P^T[b,i]
__device__ __half hUt[NZ*DD*LL];                  // U^T[a,j]
__device__ __half hQ [(size_t)NZ*LL*LL];          // Qhs probabilities
__device__ __half hHg[NZ*LL*GG];                  // Qhg probabilities
__device__ __half hT [HH*DD*DD];                  // T[h][a][b]
__device__ __half hTt[HH*DD*DD];                  // T[h][b][a]
__device__ __half hG [HH*128*DD];                 // G[h][g][a], g padded to 128
__device__ __half hGt[HH*DD*GG];                  // G^T[h][a][g]

// ---------------- mma.sync GEMM core ----------------
// BM=128, BN=128, BK=64, 128 threads (4 warps as 2m x 2n), warp tile 64x64.
#define SKA 72                   // A-normal / B smem row stride (halves)
#define SKT 136                  // A-trans smem row stride (halves)
#define TILEB 18432              // one 128x64 tile in bytes (128*72*2)
#define STAGEB (2*TILEB)         // A + B per stage (k_msg)
#define NSTG 3
#define SMEMB (NSTG*STAGEB)      // 110592 (k_msg)
#define RESOFF (2*TILEB)         // resident-operand kernels: dbuf at 0, resident at 36864
#define SMRES (4*TILEB)          // 73728 (k_S / k_proj2)

template<bool TA>
__device__ __forceinline__ void load_A(uint32_t dst, const __half* A, int lda, int kt, int tid) {
  if (!TA) {
    #pragma unroll
    for (int i = 0; i < 8; i++) {
      int idx = tid + i*128;
      int row = idx >> 3, co = (idx & 7) * 8;
      uint32_t d = dst + (row*SKA + co)*2;
      const __half* s = A + (size_t)row*lda + kt*64 + co;
      asm volatile("cp.async.cg.shared.global [%0], [%1], 16;" :: "r"(d), "l"(s));
    }
  } else {
    #pragma unroll
    for (int i = 0; i < 8; i++) {
      int idx = tid + i*128;
      int row = idx >> 4, co = (idx & 15) * 8;
      uint32_t d = dst + (row*SKT + co)*2;
      const __half* s = A + (size_t)(kt*64 + row)*lda + co;
      asm volatile("cp.async.cg.shared.global [%0], [%1], 16;" :: "r"(d), "l"(s));
    }
  }
}
__device__ __forceinline__ void load_B(uint32_t dst, const __half* B, int ldb, int kt, int tid) {
  #pragma unroll
  for (int i = 0; i < 8; i++) {
    int idx = tid + i*128;
    int row = idx >> 3, co = (idx & 7) * 8;
    uint32_t d = dst + (row*SKA + co)*2;
    const __half* s = B + (size_t)row*ldb + kt*64 + co;
    asm volatile("cp.async.cg.shared.global [%0], [%1], 16;" :: "r"(d), "l"(s));
  }
}

// ---- fragment loaders + mma (warp tile 64x64) ----
template<bool TA>
__device__ __forceinline__ void ld_afr(uint32_t (&afr)[4][4], uint32_t bufA, int kb, int wm, int lane) {
  int lr = lane & 7, sel = lane >> 3;
  #pragma unroll
  for (int mf = 0; mf < 4; mf++) {
    if (!TA) {
      int row = wm*64 + mf*16 + lr + ((sel & 1) ? 8 : 0);
      int col = kb*16 + ((sel & 2) ? 8 : 0);
      uint32_t ad = bufA + (row*SKA + col)*2;
      asm volatile("ldmatrix.sync.aligned.m8n8.x4.shared.b16 {%0,%1,%2,%3},[%4];"
        : "=r"(afr[mf][0]), "=r"(afr[mf][1]), "=r"(afr[mf][2]), "=r"(afr[mf][3]) : "r"(ad));
    } else {
      int row = kb*16 + lr + ((sel & 2) ? 8 : 0);
      int col = wm*64 + mf*16 + ((sel & 1) ? 8 : 0);
      uint32_t ad = bufA + (row*SKT + col)*2;
      asm volatile("ldmatrix.sync.aligned.m8n8.x4.trans.shared.b16 {%0,%1,%2,%3},[%4];"
        : "=r"(afr[mf][0]), "=r"(afr[mf][1]), "=r"(afr[mf][2]), "=r"(afr[mf][3]) : "r"(ad));
    }
  }
}
__device__ __forceinline__ void ld_bfr(uint32_t (&bfr)[4][4], uint32_t bufB, int kb, int wn, int lane) {
  int lr = lane & 7, sel = lane >> 3;
  #pragma unroll
  for (int p = 0; p < 4; p++) {
    int row = wn*64 + p*16 + lr + ((sel & 2) ? 8 : 0);
    int col = kb*16 + ((sel & 1) ? 8 : 0);
    uint32_t bd = bufB + (row*SKA + col)*2;
    asm volatile("ldmatrix.sync.aligned.m8n8.x4.shared.b16 {%0,%1,%2,%3},[%4];"
      : "=r"(bfr[p][0]), "=r"(bfr[p][1]), "=r"(bfr[p][2]), "=r"(bfr[p][3]) : "r"(bd));
  }
}
__device__ __forceinline__ void do_mma(float (&c)[4][8][4],
    const uint32_t (&afr)[4][4], const uint32_t (&bfr)[4][4]) {
  #pragma unroll
  for (int mf = 0; mf < 4; mf++)
    #pragma unroll
    for (int nb = 0; nb < 8; nb++) {
      asm volatile("mma.sync.aligned.m16n8k16.row.col.f32.f16.f16.f32 "
        "{%0,%1,%2,%3},{%4,%5,%6,%7},{%8,%9},{%0,%1,%2,%3};"
        : "+f"(c[mf][nb][0]), "+f"(c[mf][nb][1]), "+f"(c[mf][nb][2]), "+f"(c[mf][nb][3])
        : "r"(afr[mf][0]), "r"(afr[mf][1]), "r"(afr[mf][2]), "r"(afr[mf][3]),
          "r"(bfr[nb>>1][(nb&1)*2]), "r"(bfr[nb>>1][(nb&1)*2+1]));
    }
}

// one K=64 chunk of work (fragment double-buffered)
template<bool TA>
__device__ __forceinline__ void chunk_mma(float (&c)[4][8][4], uint32_t bufA, uint32_t bufB,
                                          int wm, int wn, int lane) {
  uint32_t afr[2][4][4], bfr[2][4][4];
  ld_afr<TA>(afr[0], bufA, 0, wm, lane);
  ld_bfr(bfr[0], bufB, 0, wn, lane);
  #pragma unroll
  for (int kb = 0; kb < 4; kb++) {
    int cur = kb & 1;
    if (kb < 3) {
      ld_afr<TA>(afr[cur^1], bufA, kb+1, wm, lane);
      ld_bfr(bfr[cur^1], bufB, kb+1, wn, lane);
    }
    do_mma(c, afr[cur], bfr[cur]);
  }
}

__device__ __forceinline__ void zero_c(float (&c)[4][8][4]) {
  #pragma unroll
  for (int i=0;i<4;i++)
    #pragma unroll
    for (int j=0;j<8;j++)
      #pragma unroll
      for (int k=0;k<4;k++) c[i][j][k] = 0.f;
}

// 3-stage pipelined GEMM (k_msg)
template<bool TA>
__device__ __forceinline__ void gemm_acc(
    const __half* A, int lda, const __half* B, int ldb, int K,
    float (&c)[4][8][4], uint32_t sbase, int tid, int wm, int wn, int lane)
{
  int NK = K >> 6;
  #pragma unroll
  for (int s = 0; s < NSTG-1; s++) {
    if (s < NK) {
      load_A<TA>(sbase + s*STAGEB, A, lda, s, tid);
      load_B(sbase + s*STAGEB + TILEB, B, ldb, s, tid);
    }
    asm volatile("cp.async.commit_group;");
  }
  for (int kt = 0; kt < NK; kt++) {
    int ps = kt + NSTG - 1;
    if (ps < NK) {
      uint32_t sb = sbase + (ps % NSTG)*STAGEB;
      load_A<TA>(sb, A, lda, ps, tid);
      load_B(sb + TILEB, B, ldb, ps, tid);
    }
    asm volatile("cp.async.commit_group;");
    asm volatile("cp.async.wait_group %0;" :: "n"(NSTG-1));
    __syncthreads();
    uint32_t bufA = sbase + (kt % NSTG)*STAGEB;
    chunk_mma<TA>(c, bufA, bufA + TILEB, wm, wn, lane);
    __syncthreads();
  }
}

// ---------------- k_proj2: operand-resident projections ----------------
// y=0: A=Qz m-tile resident; B loop {Tt[h] -> P, G[h] -> Hg}
// y=1: B=Qz j-tile resident; A loop {T[h] -> Ut, Tt[h] -> Pt}
__global__ __launch_bounds__(128, 2) void k_proj2() {
  extern __shared__ char smem[];
  uint32_t sb = (uint32_t)__cvta_generic_to_shared(smem);
  int tid = threadIdx.x, lane = tid & 31, warp = tid >> 5;
  int wm = warp >> 1, wn = warp & 1;
  int grp = blockIdx.y;
  int z = blockIdx.z, n = z >> 3, h = z & 7;
  int t0 = blockIdx.x * 128;          // m0 (grp0) or j0 (grp1)
  float c[4][8][4];
  zero_c(c);

  if (grp == 0) {
    const __half* A = hQz + (size_t)(n*LL + t0)*DD;
    const __half* Bl[2] = { hTt + h*DD*DD, hG + h*128*DD };
    // resident A at RESOFF (2 chunks); B double-buffer at 0
    load_A<false>(sb + RESOFF,         A, DD, 0, tid);
    load_A<false>(sb + RESOFF + TILEB, A, DD, 1, tid);
    load_B(sb, Bl[0], DD, 0, tid);
    asm volatile("cp.async.commit_group;");
    for (int s = 0; s < 4; s++) {
      if (s + 1 < 4)
        load_B(sb + ((s+1)&1)*TILEB, Bl[(s+1)>>1], DD, (s+1)&1, tid);
      asm volatile("cp.async.commit_group;");
      asm volatile("cp.async.wait_group 1;");
      __syncthreads();
      chunk_mma<false>(c, sb + RESOFF + (s&1)*TILEB, sb + (s&1)*TILEB, wm, wn, lane);
      if (s == 1) {
        #pragma unroll
        for (int mf = 0; mf < 4; mf++)
          #pragma unroll
          for (int rr = 0; rr < 2; rr++) {
            int row = wm*64 + mf*16 + (lane >> 2) + rr*8;
            #pragma unroll
            for (int nb = 0; nb < 8; nb++) {
              int col = wn*64 + nb*8 + (lane & 3)*2;
              *(half2*)(hP + (size_t)(z*LL + t0 + row)*DD + col) =
                  __floats2half2_rn(c[mf][nb][rr*2], c[mf][nb][rr*2+1]);
            }
          }
        zero_c(c);
      } else if (s == 3) {
        #pragma unroll
        for (int mf = 0; mf < 4; mf++)
          #pragma unroll
          for (int rr = 0; rr < 2; rr++) {
            int row = wm*64 + mf*16 + (lane >> 2) + rr*8;
            #pragma unroll
            for (int nb = 0; nb < 8; nb++) {
              int col = wn*64 + nb*8 + (lane & 3)*2;
              if (wn == 0)
                *(float2*)(g_Hg + (size_t)(z*LL + t0 + row)*GG + col) =
                    make_float2(c[mf][nb][rr*2], c[mf][nb][rr*2+1]);
            }
          }
      }
      __syncthreads();
    }
  } else {
    const __half* Bm = hQz + (size_t)(n*LL + t0)*DD;   // resident B (j-tile)
    const __half* Al[2] = { hT + h*DD*DD, hTt + h*DD*DD };
    load_B(sb + RESOFF,         Bm, DD, 0, tid);
    load_B(sb + RESOFF + TILEB, Bm, DD, 1, tid);
    load_A<false>(sb, Al[0], DD, 0, tid);
    asm volatile("cp.async.commit_group;");
    for (int s = 0; s < 4; s++) {
      if (s + 1 < 4)
        load_A<false>(sb + ((s+1)&1)*TILEB, Al[(s+1)>>1], DD, (s+1)&1, tid);
      asm volatile("cp.async.commit_group;");
      asm volatile("cp.async.wait_group 1;");
      __syncthreads();
      chunk_mma<false>(c, sb + (s&1)*TILEB, sb + RESOFF + (s&1)*TILEB, wm, wn, lane);
      if (s & 1) {
        __half* dst = (s == 1 ? hUt : hPt) + (size_t)z*DD*LL;
        #pragma unroll
        for (int mf = 0; mf < 4; mf++)
          #pragma unroll
          for (int rr = 0; rr < 2; rr++) {
            int row = wm*64 + mf*16 + (lane >> 2) + rr*8;
            #pragma unroll
            for (int nb = 0; nb < 8; nb++) {
              int col = wn*64 + nb*8 + (lane & 3)*2;
              *(half2*)(dst + (size_t)row*LL + t0 + col) =
                  __floats2half2_rn(c[mf][nb][rr*2], c[mf][nb][rr*2+1]);
            }
          }
        zero_c(c);
      }
      __syncthreads();
    }
  }
}

// ---------------- k_S: A-resident, 4 N-tiles per block, fp16 out ----------------
__global__ __launch_bounds__(128, 2) void k_S() {
  extern __shared__ char smem[];
  uint32_t sb = (uint32_t)__cvta_generic_to_shared(smem);
  int tid = threadIdx.x, lane = tid & 31, warp = tid >> 5;
  int wm = warp >> 1, wn = warp & 1;
  int z = blockIdx.z, n = z >> 3;
  int m0 = blockIdx.x * 128;
  int nbase = blockIdx.y * 4;          // 4 n-tiles per block
  const __half* A = hP + (size_t)(z*LL + m0)*DD;
  float c[4][8][4];
  zero_c(c);

  load_A<false>(sb + RESOFF,         A, DD, 0, tid);
  load_A<false>(sb + RESOFF + TILEB, A, DD, 1, tid);
  load_B(sb, hQz + (size_t)(n*LL + nbase*128)*DD, DD, 0, tid);
  asm volatile("cp.async.commit_group;");
  for (int s = 0; s < 8; s++) {
    if (s + 1 < 8) {
      int nt = (s+1) >> 1, kc = (s+1) & 1;
      load_B(sb + ((s+1)&1)*TILEB,
             hQz + (size_t)(n*LL + (nbase+nt)*128)*DD, DD, kc, tid);
    }
    asm volatile("cp.async.commit_group;");
    asm volatile("cp.async.wait_group 1;");
    __syncthreads();
    chunk_mma<false>(c, sb + RESOFF + (s&1)*TILEB, sb + (s&1)*TILEB, wm, wn, lane);
    if (s & 1) {
      int n0 = (nbase + (s>>1)) * 128;
      #pragma unroll
      for (int mf = 0; mf < 4; mf++)
        #pragma unroll
        for (int rr = 0; rr < 2; rr++) {
          int row = wm*64 + mf*16 + (lane >> 2) + rr*8;
          #pragma unroll
          for (int nb = 0; nb < 8; nb++) {
            int col = wn*64 + nb*8 + (lane & 3)*2;
            *(half2*)(g_Sh + (size_t)(z*LL + m0 + row)*LL + n0 + col) =
                __floats2half2_rn(c[mf][nb][rr*2], c[mf][nb][rr*2+1]);
          }
        }
      zero_c(c);
    }
    __syncthreads();
  }
}

// ---------------- fused msg_i + msg_j + msg_g per head, atomic into F_Z ----------------
__global__ __launch_bounds__(128, 2) void k_msg() {
  extern __shared__ char smem[];
  uint32_t sbase = (uint32_t)__cvta_generic_to_shared(smem);
  int tid = threadIdx.x, lane = tid & 31, warp = tid >> 5;
  int wm = warp >> 1, wn = warp & 1;
  int z = blockIdx.z, n = z >> 3, h = z & 7;
  int m0 = blockIdx.x * 128;
  float c[4][8][4];
  zero_c(c);

  // msg_i[i,a]: A = Q[i,j] rows m0.., B = Ut[a,j]
  gemm_acc<false>(hQ + (size_t)z*LL*LL + (size_t)m0*LL, LL,
                  hUt + (size_t)z*DD*LL, LL, LL, c, sbase, tid, wm, wn, lane);
  // msg_j[j,b]: A = Q^T via ldmatrix.trans, B = Pt[b,i]
  gemm_acc<true>(hQ + (size_t)z*LL*LL + m0, LL,
                 hPt + (size_t)z*DD*LL, LL, LL, c, sbase, tid, wm, wn, lane);
  // msg_g[i,a]: A = Qhg[i,g], B = Gt[a,g]
  gemm_acc<false>(hHg + (size_t)(z*LL + m0)*GG, GG,
                  hGt + h*DD*GG, GG, GG, c, sbase, tid, wm, wn, lane);

  float* Cb = g_FZ + (size_t)(n*LL + m0)*DD;
  #pragma unroll
  for (int mf = 0; mf < 4; mf++)
    #pragma unroll
    for (int rr = 0; rr < 2; rr++) {
      int row = wm*64 + mf*16 + (lane >> 2) + rr*8;
      #pragma unroll
      for (int nb = 0; nb < 8; nb++) {
        int col = wn*64 + nb*8 + (lane & 3)*2;
        atomicAdd(Cb + (size_t)row*DD + col,     c[mf][nb][rr*2]);
        atomicAdd(Cb + (size_t)row*DD + col + 1, c[mf][nb][rr*2+1]);
      }
    }
}

// ---------------- repack weights to fp16 (+ transposes, padding) ----------------
__global__ void k_repack(const float* __restrict__ ternary, const float* __restrict__ glob) {
  int idx = blockIdx.x*256 + threadIdx.x;     // 0..131071
  if (idx < DD*DD*HH) {
    int h = idx % HH; int ab = idx / HH; int b = ab % DD; int a = ab / DD;
    __half v = __float2half(ternary[idx]);
    hT [(h*DD + a)*DD + b] = v;
    hTt[(h*DD + b)*DD + a] = v;
  }
  {
    int h = idx / (128*DD); int rem = idx % (128*DD); int g = rem / DD; int a = rem % DD;
    float gv = (g < GG) ? glob[(g*DD + a)*HH + h] : 0.f;
    hG[idx] = __float2half(gv);
    if (g < GG) hGt[(h*DD + a)*GG + g] = __float2half(gv);
  }
}

// ---------------- softmax over D=128 -> hQz ----------------
__global__ void k_softmax_z(const float* __restrict__ x, int use_fz) {
  const float* in = use_fz ? g_FZ : x;
  int row = blockIdx.x; int t = threadIdx.x;  // 128
  float v = in[row*DD + t];
  __shared__ float r1[4], r2[4];
  float m = v;
  #pragma unroll
  for (int o=16;o;o>>=1) m = fmaxf(m, __shfl_xor_sync(0xffffffffu, m, o));
  if ((t&31)==0) r1[t>>5] = m;
  __syncthreads();
  m = fmaxf(fmaxf(r1[0],r1[1]), fmaxf(r1[2],r1[3]));
  float e = __expf(v - m);
  float s = e;
  #pragma unroll
  for (int o=16;o;o>>=1) s += __shfl_xor_sync(0xffffffffu, s, o);
  if ((t&31)==0) r2[t>>5] = s;
  __syncthreads();
  s = r2[0]+r2[1]+r2[2]+r2[3];
  hQz[row*DD + t] = __float2half(e * (1.0f/s));
}

// ---------------- softmax over concat [S row fp16 (1024) | Hg row (64)] -> hQ, hHg ----------------
__global__ void k_softmax_h(const int* __restrict__ mask) {
  int r = blockIdx.x;                 // z*L + i
  int t = threadIdx.x;                // 256
  const __half* Srow = g_Sh + (size_t)r*LL;
  const float* Hrow = g_Hg + (size_t)r*GG;
  int n = r >> 13;
  int i = r & (LL-1);
  const int* mrow = mask + n*LL;
  int mi = mrow[i];
  float v[4];
  {
    uint2 raw = *(const uint2*)(Srow + t*4);
    __half2* hp = (__half2*)&raw;
    float2 f0 = __half22float2(hp[0]);
    float2 f1 = __half22float2(hp[1]);
    v[0]=f0.x; v[1]=f0.y; v[2]=f1.x; v[3]=f1.y;
  }
  int4 mc = *(const int4*)(mrow + t*4);
  int mm[4] = {mc.x, mc.y, mc.z, mc.w};
  float lm = -3.4e38f;
  #pragma unroll
  for (int s=0;s<4;s++) {
    if (!(mi && mm[s])) v[s] = NEGV;
    lm = fmaxf(lm, v[s]);
  }
  float hgv = 0.f;
  if (t < GG) { hgv = Hrow[t]; lm = fmaxf(lm, hgv); }
  __shared__ float sm[8], ss[8];
  float w = lm;
  #pragma unroll
  for (int o=16;o;o>>=1) w = fmaxf(w, __shfl_xor_sync(0xffffffffu, w, o));
  if ((t&31)==0) sm[t>>5] = w;
  __syncthreads();
  float m = sm[0];
  #pragma unroll
  for (int q=1;q<8;q++) m = fmaxf(m, sm[q]);
  float sum = 0.f;
  #pragma unroll
  for (int s=0;s<4;s++) { v[s] = __expf(v[s]-m); sum += v[s]; }
  if (t < GG) { hgv = __expf(hgv-m); sum += hgv; }
  #pragma unroll
  for (int o=16;o;o>>=1) sum += __shfl_xor_sync(0xffffffffu, sum, o);
  if ((t&31)==0) ss[t>>5] = sum;
  __syncthreads();
  float tot = 0.f;
  #pragma unroll
  for (int q=0;q<8;q++) tot += ss[q];
  float inv = 1.0f/tot;
  __half* Qrow = hQ + (size_t)r*LL;
  {
    uint2 outp;
    __half2* op = (__half2*)&outp;
    op[0] = __floats2half2_rn(v[0]*inv, v[1]*inv);
    op[1] = __floats2half2_rn(v[2]*inv, v[3]*inv);
    *(uint2*)(Qrow + t*4) = outp;
  }
  if (t < GG) hHg[(size_t)r*GG + t] = __float2half(hgv*inv);
}

// ---------------- F_Z = x ----------------
__global__ void k_init_fz(const float* __restrict__ x) {
  int i = blockIdx.x*256 + threadIdx.x;
  g_FZ[i] = x[i];
}

// ---------------- output masking ----------------
__global__ void k_out(const int* __restrict__ mask, float* __restrict__ out) {
  int idx = blockIdx.x*256 + threadIdx.x;
  int ni = idx >> 7;
  out[idx] = mask[ni] ? g_FZ[idx] : 0.f;
}

// ---------------- launch ----------------
extern "C" void kernel_launch(void* const* d_in, const int* in_sizes, int n_in,
                              void* d_out, int out_size) {
  const float* x       = (const float*)d_in[0];
  const int*   mask    = (const int*)  d_in[1];
  const float* ternary = (const float*)d_in[2];
  const float* glob    = (const float*)d_in[3];
  float* out = (float*)d_out;

  cudaFuncSetAttribute(k_proj2, cudaFuncAttributeMaxDynamicSharedMemorySize, SMRES);
  cudaFuncSetAttribute(k_S,     cudaFuncAttributeMaxDynamicSharedMemorySize, SMRES);
  cudaFuncSetAttribute(k_msg,   cudaFuncAttributeMaxDynamicSharedMemorySize, SMEMB);

  k_repack<<<512,256>>>(ternary, glob);
  k_softmax_z<<<BB*LL, 128>>>(x, 0);

  for (int it = 0; it < NITER; it++) {
    k_proj2<<<dim3(8,2,NZ),128,SMRES>>>();    // P+Hg / Ut+Pt (operand-resident)
    k_S    <<<dim3(8,2,NZ),128,SMRES>>>();    // S logits fp16 (A-resident, 4 n-tiles)
    k_softmax_h<<<NZ*LL, 256>>>(mask);        // -> hQ, hHg
    k_init_fz<<<(BB*LL*DD)/256,256>>>(x);     // F_Z = x
    k_msg  <<<dim3(8,1,NZ),128,SMEMB>>>();    // F_Z += msg_i + msg_j + msg_g
    if (it < NITER-1) k_softmax_z<<<BB*LL, 128>>>(x, 1);
  }
  k_out<<<(BB*LL*DD)/256,256>>>(mask, out);
}